// round 7
// baseline (speedup 1.0000x reference)
#include <cuda_runtime.h>
#include <cstdint>

#define N_   128
#define C_   128
#define H_   56
#define W_   56
#define O_   32
#define KW_  3

#define ROWS    8     // output h rows per block
#define C_CH    32    // channels staged per chunk
#define NCHUNK  (C_ / C_CH)   // 4
#define THREADS 448   // 8 rows * 56 units (7 w-groups * 8 o-groups)

#define SW_ELEMS   (C_ * KW_ * O_)          // 12288 floats, layout [c][k][o]
#define SX_STRIDE_R 64                      // padded row: data at idx 4..59, zeros at 3 & 60
#define SX_STRIDE_C (ROWS * SX_STRIDE_R)    // 512
#define SX_ELEMS   (C_CH * SX_STRIDE_C)     // 16384 floats per buffer
// +SX_STRIDE_C floats of slack so the c+2 register prefetch may overread safely
#define SMEM_BYTES ((SW_ELEMS + 2 * SX_ELEMS + SX_STRIDE_C) * 4)   // 182272 B

extern __shared__ float smem_f[];

typedef unsigned long long ull;

__device__ __forceinline__ ull fma2(ull a, ull b, ull c) {
    ull d;
    asm("fma.rn.f32x2 %0, %1, %2, %3;" : "=l"(d) : "l"(a), "l"(b), "l"(c));
    return d;
}

__device__ __forceinline__ ull pack2(float x) {
    ull d;
    unsigned int u = __float_as_uint(x);
    asm("mov.b64 %0, {%1, %1};" : "=l"(d) : "r"(u));
    return d;
}

__device__ __forceinline__ float lo32(ull v) { return __uint_as_float((unsigned int)v); }
__device__ __forceinline__ float hi32(ull v) { return __uint_as_float((unsigned int)(v >> 32)); }

__device__ __forceinline__ void cp_async16(float* smem_dst, const float* gmem_src) {
    unsigned int d = (unsigned int)__cvta_generic_to_shared(smem_dst);
    asm volatile("cp.async.cg.shared.global [%0], [%1], 16;\n" :: "r"(d), "l"(gmem_src));
}
__device__ __forceinline__ void cp_commit() {
    asm volatile("cp.async.commit_group;\n");
}
__device__ __forceinline__ void cp_wait0() {
    asm volatile("cp.async.wait_group 0;\n");
}

__global__ void __launch_bounds__(THREADS, 1)
conv1x3_roll_kernel(const float* __restrict__ x,
                    const float* __restrict__ wgt,
                    float* __restrict__ out) {
    float* sw  = smem_f;                  // [c][k][o] : 128*3*32
    float* sx0 = smem_f + SW_ELEMS;       // double buffers
    float* sx1 = sx0 + SX_ELEMS;

    const int n      = blockIdx.x;
    const int h_base = blockIdx.y * ROWS;
    const int tid    = threadIdx.x;

    const int r   = tid / 56;       // 0..7 output row within tile
    const int u   = tid % 56;
    const int w_g = u >> 3;         // 0..6  -> w0 = 8*w_g
    const int o_g = u & 7;          // 0..7  -> o0 = 4*o_g
    const int w0  = w_g * 8;
    const int o0  = o_g * 4;
    const int h   = h_base + r;

    // ---- stage all weights once: sw[c][k][o] = wgt[o][c][k] ----
    for (int idx = tid; idx < SW_ELEMS; idx += THREADS) {
        int o = idx & 31;
        int k = (idx >> 5) % 3;
        int c = idx / 96;
        sw[idx] = wgt[(o * C_ + c) * KW_ + k];
    }
    // ---- zero pads (idx 3 & 60 of every row, both buffers) once ----
    for (int q = tid; q < 2 * C_CH * ROWS; q += THREADS) {
        int rr  = q % ROWS;
        int c   = (q / ROWS) % C_CH;
        float* buf = (q < C_CH * ROWS) ? sx0 : sx1;
        float* row = buf + c * SX_STRIDE_C + rr * SX_STRIDE_R;
        row[3]  = 0.0f;
        row[60] = 0.0f;
    }

    // ---- staging: chunk starting at channel c0 -> buffer buf ----
    auto stage = [&](float* buf, int c0) {
#pragma unroll
        for (int it = 0; it < (C_CH * ROWS * 14) / THREADS; ++it) {
            int q  = tid + it * THREADS;
            int v  = q % 14;
            int rr = (q / 14) % ROWS;
            int c  = q / (14 * ROWS);
            int hs = h_base + rr - 1;
            if (hs < 0) hs += H_;
            const float* src = x + (((size_t)n * C_ + (c0 + c)) * H_ + hs) * W_ + v * 4;
            float* dst = buf + c * SX_STRIDE_C + rr * SX_STRIDE_R + 4 + v * 4;
            cp_async16(dst, src);
        }
        cp_commit();
    };

    ull acc[2][8];
#pragma unroll
    for (int p = 0; p < 2; ++p)
#pragma unroll
        for (int i = 0; i < 8; ++i) acc[p][i] = 0ull;

    stage(sx0, 0);   // prologue

    for (int cc = 0; cc < NCHUNK; ++cc) {
        float* buf = (cc & 1) ? sx1 : sx0;
        const int c0 = cc * C_CH;

        cp_wait0();          // chunk cc data landed
        __syncthreads();     // all warps: data visible AND done computing cc-1

        if (cc + 1 < NCHUNK) {
            float* nbuf = (cc & 1) ? sx0 : sx1;
            stage(nbuf, c0 + C_CH);
        }

        // ---- accumulate chunk cc; software-pipelined over c ----
        const float* xbase = buf + r * SX_STRIDE_R + (w0 + 3);
        const float* wbase = sw + c0 * (KW_ * O_) + o0;

        ull xa[10], xb[10];
#pragma unroll
        for (int j = 0; j < 10; ++j) xa[j] = pack2(xbase[j]);

#pragma unroll 1
        for (int c = 0; c < C_CH; c += 2) {
            // prefetch c+1 into xb while computing c from xa
            const float* xr1 = xbase + (c + 1) * SX_STRIDE_C;
#pragma unroll
            for (int j = 0; j < 10; ++j) xb[j] = pack2(xr1[j]);
            {
                const float* wrow = wbase + c * (KW_ * O_);
#pragma unroll
                for (int k = 0; k < 3; ++k)
#pragma unroll
                    for (int p = 0; p < 2; ++p) {
                        ull wp = *reinterpret_cast<const ull*>(wrow + k * O_ + 2 * p);
#pragma unroll
                        for (int i = 0; i < 8; ++i)
                            acc[p][i] = fma2(xa[i + k], wp, acc[p][i]);
                    }
            }
            // prefetch c+2 into xa while computing c+1 from xb
            // (last iteration overreads into the +1-channel smem slack pad)
            const float* xr2 = xbase + (c + 2) * SX_STRIDE_C;
#pragma unroll
            for (int j = 0; j < 10; ++j) xa[j] = pack2(xr2[j]);
            {
                const float* wrow = wbase + (c + 1) * (KW_ * O_);
#pragma unroll
                for (int k = 0; k < 3; ++k)
#pragma unroll
                    for (int p = 0; p < 2; ++p) {
                        ull wp = *reinterpret_cast<const ull*>(wrow + k * O_ + 2 * p);
#pragma unroll
                        for (int i = 0; i < 8; ++i)
                            acc[p][i] = fma2(xb[i + k], wp, acc[p][i]);
                    }
            }
        }
    }

    // ---- write out: acc[p][i] holds (o=o0+2p, o=o0+2p+1) at w = w0+i ----
#pragma unroll
    for (int p = 0; p < 2; ++p) {
        float* dst_lo = out + (((size_t)n * O_ + (o0 + 2 * p)) * H_ + h) * W_ + w0;
        float* dst_hi = dst_lo + (size_t)H_ * W_;
        float4 a, b;
        a.x = lo32(acc[p][0]); a.y = lo32(acc[p][1]); a.z = lo32(acc[p][2]); a.w = lo32(acc[p][3]);
        b.x = lo32(acc[p][4]); b.y = lo32(acc[p][5]); b.z = lo32(acc[p][6]); b.w = lo32(acc[p][7]);
        *reinterpret_cast<float4*>(dst_lo)     = a;
        *reinterpret_cast<float4*>(dst_lo + 4) = b;
        a.x = hi32(acc[p][0]); a.y = hi32(acc[p][1]); a.z = hi32(acc[p][2]); a.w = hi32(acc[p][3]);
        b.x = hi32(acc[p][4]); b.y = hi32(acc[p][5]); b.z = hi32(acc[p][6]); b.w = hi32(acc[p][7]);
        *reinterpret_cast<float4*>(dst_hi)     = a;
        *reinterpret_cast<float4*>(dst_hi + 4) = b;
    }
}

extern "C" void kernel_launch(void* const* d_in, const int* in_sizes, int n_in,
                              void* d_out, int out_size) {
    const float* x = (const float*)d_in[0];
    const float* w = (const float*)d_in[1];
    if (n_in >= 2 && in_sizes[0] == O_ * C_ * KW_) {
        const float* t = x; x = w; w = t;
    }
    float* out = (float*)d_out;

    cudaFuncSetAttribute(conv1x3_roll_kernel,
                         cudaFuncAttributeMaxDynamicSharedMemorySize, SMEM_BYTES);

    dim3 grid(N_, H_ / ROWS);  // 128 x 7
    conv1x3_roll_kernel<<<grid, THREADS, SMEM_BYTES>>>(x, w, out);
}

// round 9
// speedup vs baseline: 2.1649x; 2.1649x over previous
#include <cuda_runtime.h>
#include <cstdint>

#define N_ 128
#define C_ 128
#define H_ 56
#define W_ 56
#define O_ 32
#define KTOT 384              // (tap, c) flattened: k = tap*128 + c

#define THREADS 512           // 16 warps: warp = (row r = wid>>2, px0 = 14*(wid&3))
#define ROWS4 4               // h rows per block
#define C_CH 32               // channels per pipelined chunk
#define NCH 4

#define SA_STRIDE 40          // floats; banks: (40k+m)%32 = 8t+g -> conflict-free
#define SX_STRIDE 72          // floats; banks: (72c+px)%32 = 8t+... -> conflict-free
#define SX_ROW   (C_CH * SX_STRIDE)            // 2304 floats (one h-row, one chunk)
#define SX_BUF   (ROWS4 * SX_ROW)              // 9216 floats
#define SA_FLOATS (KTOT * SA_STRIDE)           // 15360
#define SMEM_FLOATS (SA_FLOATS + 2 * SX_BUF)   // 33792
#define SMEM_BYTES (SMEM_FLOATS * 4)           // 135168

__device__ __align__(16) float g_packA[KTOT * O_];   // [k][m], tf32-rounded

extern __shared__ float smf[];

__device__ __forceinline__ void cp16(float* dst, const float* src) {
    unsigned int d = (unsigned int)__cvta_generic_to_shared(dst);
    asm volatile("cp.async.ca.shared.global [%0], [%1], 16;" :: "r"(d), "l"(src));
}
__device__ __forceinline__ uint32_t f2tf32(float v) {
    uint32_t b;
    asm("cvt.rna.tf32.f32 %0, %1;" : "=r"(b) : "f"(v));
    return b;
}
__device__ __forceinline__ void mma8(float* d, uint32_t a0, uint32_t a1, uint32_t a2,
                                     uint32_t a3, uint32_t b0, uint32_t b1) {
    asm volatile(
        "mma.sync.aligned.m16n8k8.row.col.f32.tf32.tf32.f32 "
        "{%0,%1,%2,%3}, {%4,%5,%6,%7}, {%8,%9}, {%0,%1,%2,%3};"
        : "+f"(d[0]), "+f"(d[1]), "+f"(d[2]), "+f"(d[3])
        : "r"(a0), "r"(a1), "r"(a2), "r"(a3), "r"(b0), "r"(b1));
}

__global__ void prep_kernel(const float* __restrict__ wgt) {
    int idx = blockIdx.x * blockDim.x + threadIdx.x;
    if (idx < KTOT * O_) {
        int k = idx >> 5, m = idx & 31;
        int tap = k >> 7, c = k & 127;
        g_packA[k * O_ + m] = __uint_as_float(f2tf32(wgt[(m * C_ + c) * 3 + tap]));
    }
}

__global__ void __launch_bounds__(THREADS, 1)
conv_mma_kernel(const float* __restrict__ x, float* __restrict__ out) {
    float* sA  = smf;                    // [k][SA_STRIDE], k = tap*128 + c (global)
    float* sX0 = smf + SA_FLOATS;        // [r][c_loc][SX_STRIDE]; value w at idx w+4
    float* sX1 = sX0 + SX_BUF;

    const int n   = blockIdx.x;
    const int bh  = blockIdx.y;
    const int tid = threadIdx.x;
    const int wid  = tid >> 5;
    const int lane = tid & 31;
    const int r    = wid >> 2;           // 0..3 h-row within block
    const int px0  = 14 * (wid & 3);     // 0,14,28,42
    const int g    = lane >> 2;          // 0..7
    const int t    = lane & 3;           // 0..3
    const int h    = bh * ROWS4 + r;

    // ---- stage A from packed gmem (L2-resident): 3072 x 16B ----
    for (int q = tid; q < (KTOT * O_) / 4; q += THREADS) {
        int k = q >> 3, mg = (q & 7) * 4;
        cp16(sA + k * SA_STRIDE + mg, g_packA + k * O_ + mg);
    }
    asm volatile("cp.async.commit_group;");

    // ---- zero pads (idx 3 = w=-1, idx 60..62 = w>=56) for every row of both bufs ----
    for (int i = tid; i < 2 * ROWS4 * C_CH; i += THREADS) {
        float* row = sX0 + i * SX_STRIDE;   // sX0/sX1 contiguous
        row[3] = 0.0f; row[60] = 0.0f; row[61] = 0.0f; row[62] = 0.0f;
    }

    // ---- chunk staging: c in [ch*32, ch*32+32) for all 4 rows ----
    auto stage = [&](float* buf, int ch) {
        for (int q = tid; q < ROWS4 * C_CH * 14; q += THREADS) {
            int j  = q % 14;
            int cl = (q / 14) & 31;
            int r2 = q / (14 * 32);
            int hs = bh * ROWS4 + r2 - 1; if (hs < 0) hs += H_;
            const float* src = x + (((size_t)n * C_ + (ch * 32 + cl)) * H_ + hs) * W_ + j * 4;
            cp16(buf + (r2 * 32 + cl) * SX_STRIDE + 4 + j * 4, src);
        }
    };

    stage(sX0, 0);
    asm volatile("cp.async.commit_group;");

    float acc[2][2][4];
#pragma unroll
    for (int mi = 0; mi < 2; ++mi)
#pragma unroll
        for (int ni = 0; ni < 2; ++ni)
#pragma unroll
            for (int e = 0; e < 4; ++e) acc[mi][ni][e] = 0.0f;

    const int baseB = px0 + g + 3;

    for (int ch = 0; ch < NCH; ++ch) {
        __syncthreads();                          // prev compute done block-wide
        if (ch + 1 < NCH) stage((ch & 1) ? sX0 : sX1, ch + 1);
        asm volatile("cp.async.commit_group;");
        if (ch < NCH - 1) asm volatile("cp.async.wait_group 1;");
        else              asm volatile("cp.async.wait_group 0;");
        __syncthreads();                          // chunk ch (+A) visible

        const float* buf = (ch & 1) ? sX1 : sX0;
        const float* sx  = buf + r * SX_ROW;      // this warp's h-row

#pragma unroll
        for (int tap = 0; tap < 3; ++tap) {
#pragma unroll
            for (int ks = 0; ks < 4; ++ks) {
                const int kg = tap * 128 + ch * 32 + ks * 8;
                const int ar = (kg + t) * SA_STRIDE + g;
                const uint32_t* ua = (const uint32_t*)sA;
                uint32_t a00 = ua[ar],        a01 = ua[ar + 8];
                uint32_t a02 = ua[ar + 160],  a03 = ua[ar + 168];   // k+4 -> +4*40
                uint32_t a10 = ua[ar + 16],   a11 = ua[ar + 24];
                uint32_t a12 = ua[ar + 176],  a13 = ua[ar + 184];

                const int br = (ks * 8 + t) * SX_STRIDE + baseB + tap;
                uint32_t b00 = f2tf32(sx[br]);
                uint32_t b01 = f2tf32(sx[br + 4 * SX_STRIDE]);
                uint32_t b10 = f2tf32(sx[br + 8]);
                uint32_t b11 = f2tf32(sx[br + 8 + 4 * SX_STRIDE]);

                mma8(acc[0][0], a00, a01, a02, a03, b00, b01);
                mma8(acc[0][1], a00, a01, a02, a03, b10, b11);
                mma8(acc[1][0], a10, a11, a12, a13, b00, b01);
                mma8(acc[1][1], a10, a11, a12, a13, b10, b11);
            }
        }
    }

    // ---- store: D row = o (16mi+g, +8), col = px0+8ni+2t (+1) ----
#pragma unroll
    for (int mi = 0; mi < 2; ++mi)
#pragma unroll
        for (int ni = 0; ni < 2; ++ni) {
            if (ni == 1 && t == 3) continue;      // px local 14,15 invalid
            int o  = 16 * mi + g;
            int px = px0 + 8 * ni + 2 * t;
            float* dst = out + (((size_t)n * O_ + o) * H_ + h) * W_ + px;
            float2 v0 = make_float2(acc[mi][ni][0], acc[mi][ni][1]);
            float2 v1 = make_float2(acc[mi][ni][2], acc[mi][ni][3]);
            *reinterpret_cast<float2*>(dst) = v0;
            *reinterpret_cast<float2*>(dst + 8 * H_ * W_) = v1;   // o+8
        }
}

extern "C" void kernel_launch(void* const* d_in, const int* in_sizes, int n_in,
                              void* d_out, int out_size) {
    const float* x = (const float*)d_in[0];
    const float* w = (const float*)d_in[1];
    if (n_in >= 2 && in_sizes[0] == O_ * C_ * 3) {
        const float* tmp = x; x = w; w = tmp;
    }
    float* out = (float*)d_out;

    prep_kernel<<<(KTOT * O_ + 255) / 256, 256>>>(w);

    cudaFuncSetAttribute(conv_mma_kernel,
                         cudaFuncAttributeMaxDynamicSharedMemorySize, SMEM_BYTES);
    dim3 grid(N_, H_ / ROWS4);   // 128 x 14
    conv_mma_kernel<<<grid, THREADS, SMEM_BYTES>>>(x, out);
}

// round 10
// speedup vs baseline: 2.3641x; 1.0920x over previous
#include <cuda_runtime.h>
#include <cstdint>

#define N_ 128
#define C_ 128
#define H_ 56
#define W_ 56
#define O_ 32
#define KTOT 384              // (tap, c) flattened: k = tap*128 + c

#define THREADS 512           // 16 warps: r = wid>>1 (8 h rows), s = wid&1 (px half)
#define ROWS8 8
#define C_CH 32
#define NCH 4

#define SA_STRIDE 40          // words; LDS.64 @ 40k+16mi+2g -> conflict-free per phase
#define SX_STRIDE 72          // words; 8t+g+const distinct over warp -> conflict-free
#define SX_ROW   (C_CH * SX_STRIDE)            // 2304 floats per h-row per chunk
#define SX_BUF   (ROWS8 * SX_ROW)              // 18432 floats
#define SA_FLOATS (KTOT * SA_STRIDE)           // 15360
#define SMEM_BYTES ((SA_FLOATS + 2 * SX_BUF) * 4)   // 208896 B

__device__ __align__(16) float g_packA[KTOT * O_];   // [k][p] interleaved, tf32-rounded

extern __shared__ float smf[];

__device__ __forceinline__ void cp16(float* dst, const float* src) {
    unsigned int d = (unsigned int)__cvta_generic_to_shared(dst);
    asm volatile("cp.async.ca.shared.global [%0], [%1], 16;" :: "r"(d), "l"(src));
}
__device__ __forceinline__ uint32_t f2tf32(float v) {
    uint32_t b;
    asm("cvt.rna.tf32.f32 %0, %1;" : "=r"(b) : "f"(v));
    return b;
}
__device__ __forceinline__ void mma8(float* d, uint32_t a0, uint32_t a1, uint32_t a2,
                                     uint32_t a3, uint32_t b0, uint32_t b1) {
    asm volatile(
        "mma.sync.aligned.m16n8k8.row.col.f32.tf32.tf32.f32 "
        "{%0,%1,%2,%3}, {%4,%5,%6,%7}, {%8,%9}, {%0,%1,%2,%3};"
        : "+f"(d[0]), "+f"(d[1]), "+f"(d[2]), "+f"(d[3])
        : "r"(a0), "r"(a1), "r"(a2), "r"(a3), "r"(b0), "r"(b1));
}

__global__ void prep_kernel(const float* __restrict__ wgt) {
    int idx = blockIdx.x * blockDim.x + threadIdx.x;
    if (idx < KTOT * O_) {
        int k = idx >> 5, m = idx & 31;
        int tap = k >> 7, c = k & 127;
        int mi = m >> 4, mm = m & 15;
        int p  = 16 * mi + 2 * (mm & 7) + (mm >> 3);   // pair-interleaved
        g_packA[k * O_ + p] = __uint_as_float(f2tf32(wgt[(m * C_ + c) * 3 + tap]));
    }
}

__global__ void __launch_bounds__(THREADS, 1)
conv_mma_kernel(const float* __restrict__ x, float* __restrict__ out) {
    float* sA  = smf;                    // [k][SA_STRIDE], interleaved p within row
    float* sX0 = smf + SA_FLOATS;        // [r][c_loc][SX_STRIDE]; value w at idx w+4
    float* sX1 = sX0 + SX_BUF;

    const int n   = blockIdx.x;
    const int bh  = blockIdx.y;
    const int tid = threadIdx.x;
    const int wid  = tid >> 5;
    const int lane = tid & 31;
    const int r    = wid >> 1;           // 0..7 h-row
    const int s    = wid & 1;            // px half: 0 -> 0..27, 1 -> 28..55
    const int g    = lane >> 2;          // 0..7
    const int t    = lane & 3;           // 0..3
    const int h    = bh * ROWS8 + r;

    // ---- stage A (L2-resident packed weights): 3072 x 16B ----
    for (int q = tid; q < (KTOT * O_) / 4; q += THREADS) {
        int k = q >> 3, pg = (q & 7) * 4;
        cp16(sA + k * SA_STRIDE + pg, g_packA + k * O_ + pg);
    }
    asm volatile("cp.async.commit_group;");

    // ---- zero pads: idx 3 (w=-1) and idx 60..71 (w>=56 + overread slack) ----
    for (int i = tid; i < 2 * ROWS8 * C_CH; i += THREADS) {
        float* row = sX0 + i * SX_STRIDE;          // sX0/sX1 contiguous
        row[3] = 0.0f;
#pragma unroll
        for (int z = 60; z < 72; ++z) row[z] = 0.0f;
    }

    auto stage = [&](float* buf, int ch) {
        for (int q = tid; q < ROWS8 * C_CH * 14; q += THREADS) {
            int j  = q % 14;
            int cl = (q / 14) & 31;
            int r2 = q / (14 * 32);
            int hs = bh * ROWS8 + r2 - 1; if (hs < 0) hs += H_;
            const float* src = x + (((size_t)n * C_ + (ch * 32 + cl)) * H_ + hs) * W_ + j * 4;
            cp16(buf + (r2 * 32 + cl) * SX_STRIDE + 4 + j * 4, src);
        }
    };

    stage(sX0, 0);
    asm volatile("cp.async.commit_group;");

    float acc[2][4][4];
#pragma unroll
    for (int mi = 0; mi < 2; ++mi)
#pragma unroll
        for (int ni = 0; ni < 4; ++ni)
#pragma unroll
            for (int e = 0; e < 4; ++e) acc[mi][ni][e] = 0.0f;

    const int baseB = 28 * s + g + 3;

    for (int ch = 0; ch < NCH; ++ch) {
        __syncthreads();                          // prev compute done block-wide
        if (ch + 1 < NCH) stage((ch & 1) ? sX0 : sX1, ch + 1);
        asm volatile("cp.async.commit_group;");
        if (ch < NCH - 1) asm volatile("cp.async.wait_group 1;");
        else              asm volatile("cp.async.wait_group 0;");
        __syncthreads();                          // chunk ch (+A) visible

        const float* buf = (ch & 1) ? sX1 : sX0;
        const float* sx  = buf + r * SX_ROW;

#pragma unroll
        for (int tap = 0; tap < 3; ++tap) {
#pragma unroll
            for (int ks = 0; ks < 4; ++ks) {
                const int kg = tap * 128 + ch * 32 + ks * 8;
                const uint32_t* ua = (const uint32_t*)sA;
                const int ar = (kg + t) * SA_STRIDE + 2 * g;

                uint2 A0  = *(const uint2*)(ua + ar);              // mi=0, k_lo
                uint2 A0h = *(const uint2*)(ua + ar + 4 * SA_STRIDE);   // mi=0, k_hi
                uint2 A1  = *(const uint2*)(ua + ar + 16);         // mi=1, k_lo
                uint2 A1h = *(const uint2*)(ua + ar + 16 + 4 * SA_STRIDE);

                const int br = (ks * 8 + t) * SX_STRIDE + baseB + tap;
                uint32_t b0[4], b1[4];
#pragma unroll
                for (int ni = 0; ni < 4; ++ni) {
                    b0[ni] = __float_as_uint(sx[br + 8 * ni]);
                    b1[ni] = __float_as_uint(sx[br + 8 * ni + 4 * SX_STRIDE]);
                }
#pragma unroll
                for (int ni = 0; ni < 4; ++ni) {
                    mma8(acc[0][ni], A0.x, A0.y, A0h.x, A0h.y, b0[ni], b1[ni]);
                    mma8(acc[1][ni], A1.x, A1.y, A1h.x, A1h.y, b0[ni], b1[ni]);
                }
            }
        }
    }

    // ---- store: lane (g,t) row o=16mi+g (+8), col px = 28s + 8ni + 2t (+1) ----
#pragma unroll
    for (int mi = 0; mi < 2; ++mi)
#pragma unroll
        for (int ni = 0; ni < 4; ++ni) {
            if (ni == 3 && t >= 2) continue;      // local px 28..31: other half / OOB
            int o  = 16 * mi + g;
            int px = 28 * s + 8 * ni + 2 * t;
            float* dst = out + (((size_t)n * O_ + o) * H_ + h) * W_ + px;
            *reinterpret_cast<float2*>(dst) =
                make_float2(acc[mi][ni][0], acc[mi][ni][1]);
            *reinterpret_cast<float2*>(dst + 8 * H_ * W_) =
                make_float2(acc[mi][ni][2], acc[mi][ni][3]);   // o+8
        }
}

extern "C" void kernel_launch(void* const* d_in, const int* in_sizes, int n_in,
                              void* d_out, int out_size) {
    const float* x = (const float*)d_in[0];
    const float* w = (const float*)d_in[1];
    if (n_in >= 2 && in_sizes[0] == O_ * C_ * 3) {
        const float* tmp = x; x = w; w = tmp;
    }
    float* out = (float*)d_out;

    prep_kernel<<<(KTOT * O_ + 255) / 256, 256>>>(w);

    cudaFuncSetAttribute(conv_mma_kernel,
                         cudaFuncAttributeMaxDynamicSharedMemorySize, SMEM_BYTES);
    dim3 grid(N_, H_ / ROWS8);   // 128 x 7
    conv_mma_kernel<<<grid, THREADS, SMEM_BYTES>>>(x, out);
}